// round 14
// baseline (speedup 1.0000x reference)
#include <cuda_runtime.h>
#include <cuda_fp16.h>
#include <cstdint>

#define Tn 17
#define Bn 4096
#define Cn 512
#define Dn 512
#define Kn 1024
#define TILE_M 128
#define TILE_N 256
#define NSTAGE 16
#define PIPE 4
#define NBLOCKS 1088

// prep tickets: weights first (gate everything), then activations
#define NT_W 544            // 544 tickets x 16 weight rows = 8704 rows
#define NT_A 1024           // 1024 tickets x 4 batch rows = 4096 rows
#define NT   (NT_W + NT_A)

// -------------------- scratch ------------------------------------------------
__device__ __align__(256) __half g_A[(size_t)Tn * Bn * Kn];  // ~143 MB
__device__ __align__(256) __half g_W[(size_t)Tn * Dn * Kn];  // ~36 MB
__device__ float g_bias[Tn * Dn];
__device__ unsigned int g_tick;
__device__ unsigned int g_wdone;
__device__ unsigned int g_rowdone[32];
__device__ unsigned int g_exit;

// -------------------- helpers ------------------------------------------------
__device__ __forceinline__ uint32_t smem_u32(const void* p) {
    uint32_t a;
    asm("{ .reg .u64 t; cvta.to.shared.u64 t, %1; cvt.u32.u64 %0, t; }"
        : "=r"(a) : "l"(p));
    return a;
}

#define SWZ(o) ((o) ^ (((o) >> 3) & 0x70))

#define CP16(smem_addr, gptr) \
    asm volatile("cp.async.cg.shared.global [%0], [%1], 16;" \
                 :: "r"((uint32_t)(smem_addr)), "l"(gptr) : "memory")
#define CP_COMMIT()  asm volatile("cp.async.commit_group;" ::: "memory")
#define CP_WAIT_2()  asm volatile("cp.async.wait_group 2;" ::: "memory")

__device__ __forceinline__ void ldsm4(uint32_t* r, uint32_t addr) {
    asm volatile("ldmatrix.sync.aligned.m8n8.x4.shared.b16 {%0,%1,%2,%3}, [%4];"
                 : "=r"(r[0]), "=r"(r[1]), "=r"(r[2]), "=r"(r[3]) : "r"(addr));
}

__device__ __forceinline__ void mma16816(float* c, const uint32_t* a,
                                         uint32_t b0, uint32_t b1) {
    asm volatile(
        "mma.sync.aligned.m16n8k16.row.col.f32.f16.f16.f32 "
        "{%0,%1,%2,%3}, {%4,%5,%6,%7}, {%8,%9}, {%0,%1,%2,%3};"
        : "+f"(c[0]), "+f"(c[1]), "+f"(c[2]), "+f"(c[3])
        : "r"(a[0]), "r"(a[1]), "r"(a[2]), "r"(a[3]), "r"(b0), "r"(b1));
}

// SMEM: PIPE x (A 16K | B 32K) = 4 x 48K = 192K
#define STAGE_BYTES 49152u
#define SMEM_TOTAL  (PIPE * STAGE_BYTES)

__device__ __forceinline__ void write_h(__half* ph, float4 v) {
    float a[4] = {v.x, v.y, v.z, v.w};
    uint2 uh;
    unsigned short h[4];
#pragma unroll
    for (int i = 0; i < 4; ++i) h[i] = __half_as_ushort(__float2half_rn(a[i]));
    uh.x = (uint32_t)h[0] | ((uint32_t)h[1] << 16);
    uh.y = (uint32_t)h[2] | ((uint32_t)h[3] << 16);
    *reinterpret_cast<uint2*>(ph) = uh;
}

// -------------------- prep ticket bodies --------------------------------------
__device__ void prep_weight_ticket(int T, int tid,
                                   const float* __restrict__ Ws,
                                   const float* __restrict__ Wt,
                                   const float* __restrict__ bs,
                                   const float* __restrict__ bt) {
#pragma unroll
    for (int p = 0; p < 4; ++p) {
        const int row = T * 16 + p * 4 + (tid >> 7);
        const int cc  = tid & 127;
        float4 s = reinterpret_cast<const float4*>(Ws)[(size_t)row * 128 + cc];
        float4 t = reinterpret_cast<const float4*>(Wt)[(size_t)row * 128 + cc];
        const size_t wrow = (size_t)row * Kn;
        write_h(g_W + wrow + cc * 4,       s);
        write_h(g_W + wrow + 512 + cc * 4, t);
    }
    if (T < 17) {
        const int gid = T * 512 + tid;
        g_bias[gid] = bs[gid] + bt[gid];
    }
}

__device__ void prep_act_ticket(int T, int tid, const float* __restrict__ x) {
    const int b  = (T - NT_W) * 4 + (tid >> 7);
    const int c4 = tid & 127;
    const float4* xb = reinterpret_cast<const float4*>(x) + (size_t)b * (Tn * Cn / 4);

    float4 v[Tn];
    float sx = 0.f, sy = 0.f, sz = 0.f, sw = 0.f;
#pragma unroll
    for (int t = 0; t < Tn; ++t) {
        v[t] = xb[t * (Cn / 4) + c4];
        sx += v[t].x; sy += v[t].y; sz += v[t].z; sw += v[t].w;
    }
    const float4 x0 = v[0];
    const float4 xl = v[Tn - 1];
    const float inv = 1.0f / 37.0f;

#pragma unroll
    for (int t = 0; t < Tn; ++t) {
        const float a = (float)(18 - t);
        const float c = (float)(t + 2);
        float4 tr, se;
        tr.x = (sx + a * x0.x + c * xl.x) * inv;
        tr.y = (sy + a * x0.y + c * xl.y) * inv;
        tr.z = (sz + a * x0.z + c * xl.z) * inv;
        tr.w = (sw + a * x0.w + c * xl.w) * inv;
        se.x = v[t].x - tr.x; se.y = v[t].y - tr.y;
        se.z = v[t].z - tr.z; se.w = v[t].w - tr.w;
        const size_t row = ((size_t)t * Bn + b) * Kn;
        write_h(g_A + row + c4 * 4,       se);
        write_h(g_A + row + 512 + c4 * 4, tr);
    }
}

// -------------------- GEMM stage loader ---------------------------------------
__device__ __forceinline__ void load_stage(int s, int buf, int tid,
                                           size_t rowA0, size_t rowB0, uint32_t sb) {
    const size_t colByte = (size_t)s * 128;
    const uint32_t st = sb + (uint32_t)buf * STAGE_BYTES;
    const char* gA = (const char*)g_A;
    const char* gW = (const char*)g_W;
#pragma unroll
    for (int i = 0; i < 2; ++i) {           // A: 1024 lines / 512 thr
        const int idx = tid + i * 512;
        const int r = idx >> 3;
        const int cb = (idx & 7) * 16;
        const uint32_t sw = SWZ((uint32_t)(r * 128 + cb));
        CP16(st + sw, gA + (rowA0 + r) * (Kn * 2) + colByte + cb);
    }
#pragma unroll
    for (int i = 0; i < 4; ++i) {           // B: 2048 lines / 512 thr
        const int idx = tid + i * 512;
        const int r = idx >> 3;
        const int cb = (idx & 7) * 16;
        const uint32_t sw = SWZ((uint32_t)(r * 128 + cb));
        CP16(st + 16384u + sw, gW + (rowB0 + r) * (Kn * 2) + colByte + cb);
    }
}

// -------------------- fused kernel: ticket prep + spin + champion GEMM --------
__global__ __launch_bounds__(512, 1) void fused_kernel(
    float* __restrict__ out, const float* __restrict__ x,
    const float* __restrict__ Ws, const float* __restrict__ Wt,
    const float* __restrict__ bs, const float* __restrict__ bt) {
    extern __shared__ char smem[];
    __shared__ unsigned int sT;
    const uint32_t sb = smem_u32(smem);
    const int tid = threadIdx.x, wid = tid >> 5, lane = tid & 31;
    const int bn = blockIdx.x, bm = blockIdx.y, t = blockIdx.z;

    // ================= Phase A: drain prep ticket pool =================
    for (;;) {
        if (tid == 0) sT = atomicAdd(&g_tick, 1u);
        __syncthreads();
        const unsigned int T = sT;
        __syncthreads();                 // sT stable before next overwrite
        if (T >= NT) break;
        if (T < NT_W) {
            prep_weight_ticket((int)T, tid, Ws, Wt, bs, bt);
            __threadfence();
            __syncthreads();             // all CTA threads done before count
            if (tid == 0) atomicAdd(&g_wdone, 1u);
        } else {
            prep_act_ticket((int)T, tid, x);
            __threadfence();
            __syncthreads();
            if (tid == 0) atomicAdd(&g_rowdone[(T - NT_W) >> 5], 1u);
        }
    }

    // ================= Spin: weights + my bm's A rows ready =================
    if (tid == 0) {
        while (*(volatile unsigned int*)&g_wdone != NT_W) __nanosleep(200);
        while (*(volatile unsigned int*)&g_rowdone[bm] != 32u) __nanosleep(200);
    }
    __syncthreads();

    // ================= Phase B: champion GEMM =================
    const int wm = wid & 3;
    const int wn = wid >> 2;
    const int mbase = wm * 32;
    const int nbase = wn * 64;

    const int tid8 = lane >> 3;
    const int r8   = lane & 7;
    const int rowOff = ((tid8 & 1) << 3) + r8;
    const int colOff = (tid8 >> 1) << 4;

    uint32_t aRow[2], aXor[2], bRow[4], bXor[4];
#pragma unroll
    for (int mf = 0; mf < 2; ++mf) {
        aRow[mf] = (uint32_t)(mbase + mf * 16 + rowOff) * 128u;
        aXor[mf] = (aRow[mf] >> 3) & 0x70u;
    }
#pragma unroll
    for (int g = 0; g < 4; ++g) {
        const uint32_t rb = (uint32_t)(nbase + g * 16 + rowOff) * 128u;
        bRow[g] = rb + 16384u;
        bXor[g] = (rb >> 3) & 0x70u;
    }

    const size_t rowA0 = (size_t)t * Bn + (size_t)bm * TILE_M;
    const size_t rowB0 = (size_t)t * Dn + (size_t)bn * TILE_N;

    float acc[2][8][4];
#pragma unroll
    for (int i = 0; i < 2; ++i)
#pragma unroll
        for (int j = 0; j < 8; ++j)
#pragma unroll
            for (int q = 0; q < 4; ++q) acc[i][j][q] = 0.f;

    load_stage(0, 0, tid, rowA0, rowB0, sb); CP_COMMIT();
    load_stage(1, 1, tid, rowA0, rowB0, sb); CP_COMMIT();
    load_stage(2, 2, tid, rowA0, rowB0, sb); CP_COMMIT();

    for (int ks = 0; ks < NSTAGE; ++ks) {
        const int buf = ks % PIPE;
        CP_WAIT_2();
        __syncthreads();
        if (ks + 3 < NSTAGE) load_stage(ks + 3, (ks + 3) % PIPE, tid, rowA0, rowB0, sb);
        CP_COMMIT();

        const uint32_t st = sb + (uint32_t)buf * STAGE_BYTES;

#pragma unroll
        for (int kk = 0; kk < 4; ++kk) {
            const uint32_t kcb = (uint32_t)(kk * 32 + colOff);
            uint32_t ah[2][4], bh[4][4];
#pragma unroll
            for (int mf = 0; mf < 2; ++mf)
                ldsm4(ah[mf], st + aRow[mf] + (kcb ^ aXor[mf]));
#pragma unroll
            for (int g = 0; g < 4; ++g)
                ldsm4(bh[g], st + bRow[g] + (kcb ^ bXor[g]));
#pragma unroll
            for (int mf = 0; mf < 2; ++mf)
#pragma unroll
                for (int g = 0; g < 4; ++g) {
                    mma16816(acc[mf][g * 2 + 0], ah[mf], bh[g][0], bh[g][2]);
                    mma16816(acc[mf][g * 2 + 1], ah[mf], bh[g][1], bh[g][3]);
                }
        }
    }

    // -------------------- epilogue: bias + store --------------------
    const int qrow = lane >> 2;
    const int qcol = (lane & 3) * 2;
#pragma unroll
    for (int mf = 0; mf < 2; ++mf) {
        const size_t row0 = (size_t)bm * TILE_M + mbase + mf * 16 + qrow;
#pragma unroll
        for (int nf = 0; nf < 8; ++nf) {
            const int col = bn * TILE_N + nbase + nf * 8 + qcol;
            const float2 bv = *reinterpret_cast<const float2*>(g_bias + t * Dn + col);
            float2 o0, o1;
            o0.x = acc[mf][nf][0] + bv.x;
            o0.y = acc[mf][nf][1] + bv.y;
            o1.x = acc[mf][nf][2] + bv.x;
            o1.y = acc[mf][nf][3] + bv.y;
            *reinterpret_cast<float2*>(out + row0 * (Tn * Dn) + (size_t)t * Dn + col) = o0;
            *reinterpret_cast<float2*>(out + (row0 + 8) * (Tn * Dn) + (size_t)t * Dn + col) = o1;
        }
    }

    // ================= self-reset for graph replay =================
    __syncthreads();
    if (tid == 0) {
        __threadfence();
        const unsigned int n = atomicAdd(&g_exit, 1u);
        if (n == NBLOCKS - 1) {   // last CTA resets all counters
            g_tick = 0u;
            g_wdone = 0u;
#pragma unroll
            for (int i = 0; i < 32; ++i) g_rowdone[i] = 0u;
            __threadfence();
            g_exit = 0u;
        }
    }
}

// ---------------------------------------------------------------------------
extern "C" void kernel_launch(void* const* d_in, const int* in_sizes, int n_in,
                              void* d_out, int out_size) {
    const float* x  = (const float*)d_in[0];
    const float* Ws = (const float*)d_in[1];
    const float* bs = (const float*)d_in[2];
    const float* Wt = (const float*)d_in[3];
    const float* bt = (const float*)d_in[4];
    float* out = (float*)d_out;

    cudaFuncSetAttribute(fused_kernel, cudaFuncAttributeMaxDynamicSharedMemorySize, SMEM_TOTAL);

    dim3 grid(Dn / TILE_N, Bn / TILE_M, Tn);   // (2, 32, 17) = 1088 CTAs
    fused_kernel<<<grid, 512, SMEM_TOTAL>>>(out, x, Ws, Wt, bs, bt);
}

// round 15
// speedup vs baseline: 1.2119x; 1.2119x over previous
#include <cuda_runtime.h>
#include <cuda_fp16.h>
#include <cstdint>

#define Tn 17
#define Bn 4096
#define Cn 512
#define Dn 512
#define Kn 1024
#define TILE_M 128
#define TILE_N 256
#define NSTAGE 16
#define PIPE 4

// -------------------- scratch ------------------------------------------------
__device__ __align__(256) __half g_A[(size_t)Tn * Bn * Kn];  // ~143 MB
__device__ __align__(256) __half g_W[(size_t)Tn * Dn * Kn];  // ~36 MB
__device__ float g_bias[Tn * Dn];

// -------------------- helpers ------------------------------------------------
__device__ __forceinline__ uint32_t smem_u32(const void* p) {
    uint32_t a;
    asm("{ .reg .u64 t; cvta.to.shared.u64 t, %1; cvt.u32.u64 %0, t; }"
        : "=r"(a) : "l"(p));
    return a;
}

#define SWZ(o) ((o) ^ (((o) >> 3) & 0x70))

#define CP16(smem_addr, gptr) \
    asm volatile("cp.async.cg.shared.global [%0], [%1], 16;" \
                 :: "r"((uint32_t)(smem_addr)), "l"(gptr) : "memory")
#define CP_COMMIT()  asm volatile("cp.async.commit_group;" ::: "memory")
#define CP_WAIT_2()  asm volatile("cp.async.wait_group 2;" ::: "memory")

__device__ __forceinline__ void ldsm4(uint32_t* r, uint32_t addr) {
    asm volatile("ldmatrix.sync.aligned.m8n8.x4.shared.b16 {%0,%1,%2,%3}, [%4];"
                 : "=r"(r[0]), "=r"(r[1]), "=r"(r[2]), "=r"(r[3]) : "r"(addr));
}

__device__ __forceinline__ void mma16816(float* c, const uint32_t* a,
                                         uint32_t b0, uint32_t b1) {
    asm volatile(
        "mma.sync.aligned.m16n8k16.row.col.f32.f16.f16.f32 "
        "{%0,%1,%2,%3}, {%4,%5,%6,%7}, {%8,%9}, {%0,%1,%2,%3};"
        : "+f"(c[0]), "+f"(c[1]), "+f"(c[2]), "+f"(c[3])
        : "r"(a[0]), "r"(a[1]), "r"(a[2]), "r"(a[3]), "r"(b0), "r"(b1));
}

// SMEM: PIPE x (A 16K | B 32K) = 4 x 48K = 192K
#define STAGE_BYTES 49152u
#define SMEM_TOTAL  (PIPE * STAGE_BYTES)

// -------------------- fused prep: activations + weights + bias ---------------
__device__ __forceinline__ void write_h(__half* ph, float4 v) {
    float a[4] = {v.x, v.y, v.z, v.w};
    uint2 uh;
    unsigned short h[4];
#pragma unroll
    for (int i = 0; i < 4; ++i) h[i] = __half_as_ushort(__float2half_rn(a[i]));
    uh.x = (uint32_t)h[0] | ((uint32_t)h[1] << 16);
    uh.y = (uint32_t)h[2] | ((uint32_t)h[3] << 16);
    *reinterpret_cast<uint2*>(ph) = uh;
}

#define WUNITS_PER_BLOCK 272   // 17*512*128 / 4096

__global__ void prep_kernel(const float* __restrict__ x,
                            const float* __restrict__ Ws, const float* __restrict__ Wt,
                            const float* __restrict__ bs, const float* __restrict__ bt) {
    const int b  = blockIdx.x;
    const int c4 = threadIdx.x;  // 0..127

    // ---- activation prep (one batch row per block) ----
    const float4* xb = reinterpret_cast<const float4*>(x) + (size_t)b * (Tn * Cn / 4);
    float4 v[Tn];
    float sx = 0.f, sy = 0.f, sz = 0.f, sw = 0.f;
#pragma unroll
    for (int t = 0; t < Tn; ++t) {
        v[t] = xb[t * (Cn / 4) + c4];
        sx += v[t].x; sy += v[t].y; sz += v[t].z; sw += v[t].w;
    }
    const float4 x0 = v[0];
    const float4 xl = v[Tn - 1];
    const float inv = 1.0f / 37.0f;

#pragma unroll
    for (int t = 0; t < Tn; ++t) {
        const float a = (float)(18 - t);
        const float c = (float)(t + 2);
        float4 tr, se;
        tr.x = (sx + a * x0.x + c * xl.x) * inv;
        tr.y = (sy + a * x0.y + c * xl.y) * inv;
        tr.z = (sz + a * x0.z + c * xl.z) * inv;
        tr.w = (sw + a * x0.w + c * xl.w) * inv;
        se.x = v[t].x - tr.x; se.y = v[t].y - tr.y;
        se.z = v[t].z - tr.z; se.w = v[t].w - tr.w;
        const size_t row = ((size_t)t * Bn + b) * Kn;
        write_h(g_A + row + c4 * 4,       se);
        write_h(g_A + row + 512 + c4 * 4, tr);
    }

    // ---- weight prep (272 float4-units per block, exact cover) ----
    {
        const size_t base = (size_t)b * WUNITS_PER_BLOCK;
#pragma unroll
        for (int p = 0; p < 3; ++p) {
            const int u = c4 + p * 128;
            if (u < WUNITS_PER_BLOCK) {
                const size_t gidw = base + u;
                const size_t row = gidw >> 7;
                const int    cc  = (int)(gidw & 127);
                float4 s = reinterpret_cast<const float4*>(Ws)[row * 128 + cc];
                float4 t = reinterpret_cast<const float4*>(Wt)[row * 128 + cc];
                const size_t wrow = row * Kn;
                write_h(g_W + wrow + cc * 4,       s);
                write_h(g_W + wrow + 512 + cc * 4, t);
            }
        }
    }

    // ---- bias (first 68 blocks x 128 threads = 8704 exact) ----
    if (b < 68) {
        const int gid = b * 128 + c4;
        g_bias[gid] = bs[gid] + bt[gid];
    }

    // PDL: allow the dependent GEMM grid to launch; its griddepcontrol.wait
    // blocks until this grid's memory is flushed.
    cudaTriggerProgrammaticLaunchCompletion();
}

// -------------------- mma.sync grouped GEMM (champion core + PDL wait) -------
__device__ __forceinline__ void load_stage(int s, int buf, int tid,
                                           size_t rowA0, size_t rowB0, uint32_t sb) {
    const size_t colByte = (size_t)s * 128;
    const uint32_t st = sb + (uint32_t)buf * STAGE_BYTES;
    const char* gA = (const char*)g_A;
    const char* gW = (const char*)g_W;
#pragma unroll
    for (int i = 0; i < 2; ++i) {           // A: 1024 lines / 512 thr
        const int idx = tid + i * 512;
        const int r = idx >> 3;
        const int cb = (idx & 7) * 16;
        const uint32_t sw = SWZ((uint32_t)(r * 128 + cb));
        CP16(st + sw, gA + (rowA0 + r) * (Kn * 2) + colByte + cb);
    }
#pragma unroll
    for (int i = 0; i < 4; ++i) {           // B: 2048 lines / 512 thr
        const int idx = tid + i * 512;
        const int r = idx >> 3;
        const int cb = (idx & 7) * 16;
        const uint32_t sw = SWZ((uint32_t)(r * 128 + cb));
        CP16(st + 16384u + sw, gW + (rowB0 + r) * (Kn * 2) + colByte + cb);
    }
}

__global__ __launch_bounds__(512, 1) void gemm_kernel(float* __restrict__ out) {
    extern __shared__ char smem[];
    const uint32_t sb = smem_u32(smem);
    const int tid = threadIdx.x, wid = tid >> 5, lane = tid & 31;
    const int bn = blockIdx.x, bm = blockIdx.y, t = blockIdx.z;

    // ---- all setup BEFORE the dependency wait (overlaps with prep) ----
    const int wm = wid & 3;
    const int wn = wid >> 2;
    const int mbase = wm * 32;
    const int nbase = wn * 64;

    const int tid8 = lane >> 3;
    const int r8   = lane & 7;
    const int rowOff = ((tid8 & 1) << 3) + r8;
    const int colOff = (tid8 >> 1) << 4;

    uint32_t aRow[2], aXor[2], bRow[4], bXor[4];
#pragma unroll
    for (int mf = 0; mf < 2; ++mf) {
        aRow[mf] = (uint32_t)(mbase + mf * 16 + rowOff) * 128u;
        aXor[mf] = (aRow[mf] >> 3) & 0x70u;
    }
#pragma unroll
    for (int g = 0; g < 4; ++g) {
        const uint32_t rb = (uint32_t)(nbase + g * 16 + rowOff) * 128u;
        bRow[g] = rb + 16384u;
        bXor[g] = (rb >> 3) & 0x70u;
    }

    const size_t rowA0 = (size_t)t * Bn + (size_t)bm * TILE_M;
    const size_t rowB0 = (size_t)t * Dn + (size_t)bn * TILE_N;

    float acc[2][8][4];
#pragma unroll
    for (int i = 0; i < 2; ++i)
#pragma unroll
        for (int j = 0; j < 8; ++j)
#pragma unroll
            for (int q = 0; q < 4; ++q) acc[i][j][q] = 0.f;

    // ---- wait for prep grid's stores to be visible, then go ----
    cudaGridDependencySynchronize();

    load_stage(0, 0, tid, rowA0, rowB0, sb); CP_COMMIT();
    load_stage(1, 1, tid, rowA0, rowB0, sb); CP_COMMIT();
    load_stage(2, 2, tid, rowA0, rowB0, sb); CP_COMMIT();

    for (int ks = 0; ks < NSTAGE; ++ks) {
        const int buf = ks % PIPE;
        CP_WAIT_2();
        __syncthreads();   // single barrier per stage (PIPE=4, distance 3)
        if (ks + 3 < NSTAGE) load_stage(ks + 3, (ks + 3) % PIPE, tid, rowA0, rowB0, sb);
        CP_COMMIT();

        const uint32_t st = sb + (uint32_t)buf * STAGE_BYTES;

#pragma unroll
        for (int kk = 0; kk < 4; ++kk) {
            const uint32_t kcb = (uint32_t)(kk * 32 + colOff);
            uint32_t ah[2][4], bh[4][4];
#pragma unroll
            for (int mf = 0; mf < 2; ++mf)
                ldsm4(ah[mf], st + aRow[mf] + (kcb ^ aXor[mf]));
#pragma unroll
            for (int g = 0; g < 4; ++g)
                ldsm4(bh[g], st + bRow[g] + (kcb ^ bXor[g]));
#pragma unroll
            for (int mf = 0; mf < 2; ++mf)
#pragma unroll
                for (int g = 0; g < 4; ++g) {
                    mma16816(acc[mf][g * 2 + 0], ah[mf], bh[g][0], bh[g][2]);
                    mma16816(acc[mf][g * 2 + 1], ah[mf], bh[g][1], bh[g][3]);
                }
        }
    }

    // -------------------- epilogue: bias + store --------------------
    const int qrow = lane >> 2;
    const int qcol = (lane & 3) * 2;
#pragma unroll
    for (int mf = 0; mf < 2; ++mf) {
        const size_t row0 = (size_t)bm * TILE_M + mbase + mf * 16 + qrow;
#pragma unroll
        for (int nf = 0; nf < 8; ++nf) {
            const int col = bn * TILE_N + nbase + nf * 8 + qcol;
            const float2 bv = *reinterpret_cast<const float2*>(g_bias + t * Dn + col);
            float2 o0, o1;
            o0.x = acc[mf][nf][0] + bv.x;
            o0.y = acc[mf][nf][1] + bv.y;
            o1.x = acc[mf][nf][2] + bv.x;
            o1.y = acc[mf][nf][3] + bv.y;
            *reinterpret_cast<float2*>(out + row0 * (Tn * Dn) + (size_t)t * Dn + col) = o0;
            *reinterpret_cast<float2*>(out + (row0 + 8) * (Tn * Dn) + (size_t)t * Dn + col) = o1;
        }
    }
}

// ---------------------------------------------------------------------------
extern "C" void kernel_launch(void* const* d_in, const int* in_sizes, int n_in,
                              void* d_out, int out_size) {
    const float* x  = (const float*)d_in[0];
    const float* Ws = (const float*)d_in[1];
    const float* bs = (const float*)d_in[2];
    const float* Wt = (const float*)d_in[3];
    const float* bt = (const float*)d_in[4];
    float* out = (float*)d_out;

    cudaFuncSetAttribute(gemm_kernel, cudaFuncAttributeMaxDynamicSharedMemorySize, SMEM_TOTAL);

    prep_kernel<<<Bn, 128>>>(x, Ws, Wt, bs, bt);

    // PDL launch: GEMM may begin launching while prep is still running; its
    // griddepcontrol.wait gates the dependent loads.
    cudaLaunchConfig_t cfg = {};
    cfg.gridDim = dim3(Dn / TILE_N, Bn / TILE_M, Tn);
    cfg.blockDim = dim3(512, 1, 1);
    cfg.dynamicSmemBytes = SMEM_TOTAL;
    cfg.stream = 0;
    cudaLaunchAttribute attrs[1];
    attrs[0].id = cudaLaunchAttributeProgrammaticStreamSerialization;
    attrs[0].val.programmaticStreamSerializationAllowed = 1;
    cfg.attrs = attrs;
    cfg.numAttrs = 1;
    cudaLaunchKernelEx(&cfg, gemm_kernel, out);
}